// round 9
// baseline (speedup 1.0000x reference)
#include <cuda_runtime.h>
#include <cstdint>

#define BB 16
#define DD 128
#define MM 4096
#define VV 32000
#define BM (BB*MM)

// ---------------- scratch (static device globals; no allocation) ----------------
__device__ __align__(16) float g_u[BB*DD];   // current query u  [B][D]
__device__ __align__(16) float g_t[BB*VV];   // score table t[b][v] = C_h[v].u[b]
__device__ __align__(16) float g_w[BB*VV];   // scattered (unnormalized) exp weights
__device__ float g_sum[BB];                  // softmax denominators
__device__ int g_is64;                       // story dtype flag (1 if int64)

// ---------------- helpers ----------------
__device__ __forceinline__ int4 load_toks(const int* __restrict__ story, int idx) {
    if (!g_is64) {
        return ((const int4*)story)[idx];
    } else {
        longlong4 l = ((const longlong4*)story)[idx];
        return make_int4((int)l.x, (int)l.y, (int)l.z, (int)l.w);
    }
}

__device__ __forceinline__ uint64_t packf2(float x, float y) {
    uint64_t r;
    asm("mov.b64 %0, {%1, %2};" : "=l"(r) : "f"(x), "f"(y));
    return r;
}
__device__ __forceinline__ void unpackf2(uint64_t v, float& x, float& y) {
    asm("mov.b64 {%0, %1}, %2;" : "=f"(x), "=f"(y) : "l"(v));
}
// packed dual-FMA: acc.{lo,hi} += a.{lo,hi} * b.{lo,hi}
__device__ __forceinline__ void ffma2(uint64_t& acc, uint64_t a, uint64_t b) {
    asm("fma.rn.f32x2 %0, %1, %2, %0;" : "+l"(acc) : "l"(a), "l"(b));
}

// ---------------- kernels ----------------

#define TILES 4          // tiles per block
#define TR    16         // rows per tile
#define DOT_T 256        // threads per k_dot block (8 warps)

// t[b][v] = dot(C_h[v], u[b]) for all v,b.   Grid MUST be 500 x 256.
// R7 pipeline (4 tiles, double-buffered cp.async, load t+2 while compute t)
// with 8 warps/block: each warp covers 4 rows/tile ->
//   rowgrp = warp>>1 (0..3) -> rows [4*rowgrp, 4*rowgrp+4) ; bgrp = warp&1
//   lane: b = bgrp*8 + (lane>>2), quarter q = lane&3 -> dims [32q, 32q+32)
// Compute interleaves row pairs (4 independent FFMA2 chains, 2 indep LDS).
template <bool FIRST, bool ZERO_W, bool COPY_U, bool USE_GU>
__global__ void __launch_bounds__(DOT_T) k_dot(const float* __restrict__ Ch,
                                               const float* __restrict__ uin,
                                               float* __restrict__ u_out,
                                               const int* __restrict__ story) {
    if (ZERO_W) {
        int j = blockIdx.x*DOT_T + threadIdx.x;        // 128000 threads == BB*VV/4
        if (j < BB*VV/4) ((float4*)g_w)[j] = make_float4(0.f, 0.f, 0.f, 0.f);
        if (blockIdx.x == 0 && threadIdx.x < BB) g_sum[threadIdx.x] = 0.f;
    }
    if (FIRST && blockIdx.x == 0) {
        for (int j = threadIdx.x; j < BB*DD; j += DOT_T) g_u[j] = uin[j];
        if (threadIdx.x == 0) {
            // int64 little-endian: odd words are high words of small tokens -> 0
            int z = story[1] | story[3] | story[5] | story[7];
            g_is64 = (z == 0) ? 1 : 0;
        }
    }
    if (COPY_U && blockIdx.x == 0) {
        for (int j = threadIdx.x; j < BB*DD; j += DOT_T) u_out[j] = g_u[j];
    }

    __shared__ __align__(16) ulonglong2 rowbuf[2][TR][32];  // 2 x 8KB buffers

    const int tid  = threadIdx.x;
    const int warp = tid >> 5;
    const int lane = tid & 31;
    const int rowgrp = warp >> 1;            // 0..3 -> 4 rows each
    const int bgrp   = warp & 1;
    const int b      = bgrp*8 + (lane >> 2);
    const int q      = lane & 3;
    const int rbase  = rowgrp * 4;

    const int base_v = blockIdx.x * (TILES*TR);

    const int c_row0 = tid >> 5;             // + k*8, k<2 -> 16 rows
    const int c_col  = tid & 31;

    // ---- async tile loader: tile tt -> buffer buf (one commit group per tile)
    auto load_tile = [&](int buf, int tt) {
        uint32_t sbase = (uint32_t)__cvta_generic_to_shared(&rowbuf[buf][0][0]);
        const float* src = Ch + (size_t)(base_v + tt*TR) * DD;
        #pragma unroll
        for (int k = 0; k < 2; k++) {
            const int row = c_row0 + k*8;
            const float4* gp = (const float4*)(src + (size_t)row * DD) + c_col;
            uint32_t sp = sbase + (row*32 + c_col)*16;
            asm volatile("cp.async.cg.shared.global [%0], [%1], 16;\n"
                         :: "r"(sp), "l"(gp));
        }
        asm volatile("cp.async.commit_group;\n");
    };

    load_tile(0, 0);

    // ---- u registers (overlap with first load): quarter = 32 floats
    uint64_t ureg[16];
    {
        const float4* u4 = USE_GU ? (const float4*)g_u : (const float4*)uin;
        #pragma unroll
        for (int s = 0; s < 8; s++) {
            float4 uu = u4[b*32 + q*8 + s];
            ureg[2*s]   = packf2(uu.x, uu.y);
            ureg[2*s+1] = packf2(uu.z, uu.w);
        }
    }

    load_tile(1, 1);

    #pragma unroll
    for (int t = 0; t < TILES; t++) {
        const int buf = t & 1;
        if (t < TILES - 1) asm volatile("cp.async.wait_group 1;\n" ::: "memory");
        else               asm volatile("cp.async.wait_group 0;\n" ::: "memory");
        __syncthreads();

        // ---- compute 4 rows as 2 interleaved row-pairs
        float tacc[4];
        #pragma unroll
        for (int rp = 0; rp < 2; rp++) {
            uint64_t a00 = packf2(0.f, 0.f), a01 = packf2(0.f, 0.f);
            uint64_t a10 = packf2(0.f, 0.f), a11 = packf2(0.f, 0.f);
            const ulonglong2* row0 = rowbuf[buf][rbase + 2*rp];
            const ulonglong2* row1 = rowbuf[buf][rbase + 2*rp + 1];
            #pragma unroll
            for (int j = 0; j < 8; j++) {
                const int s = (j + q) & 7;             // bank-stagger across quarters
                ulonglong2 c0 = row0[q*8 + s];         // two independent LDS.128
                ulonglong2 c1 = row1[q*8 + s];
                ffma2(a00, c0.x, ureg[2*s]);
                ffma2(a10, c1.x, ureg[2*s]);
                ffma2(a01, c0.y, ureg[2*s+1]);
                ffma2(a11, c1.y, ureg[2*s+1]);
            }
            float x0, x1, x2, x3, y0, y1, y2, y3;
            unpackf2(a00, x0, x1); unpackf2(a01, x2, x3);
            unpackf2(a10, y0, y1); unpackf2(a11, y2, y3);
            float s0 = (x0 + x1) + (x2 + x3);
            float s1 = (y0 + y1) + (y2 + y3);
            s0 += __shfl_down_sync(0xffffffffu, s0, 2);
            s1 += __shfl_down_sync(0xffffffffu, s1, 2);
            s0 += __shfl_down_sync(0xffffffffu, s0, 1);
            s1 += __shfl_down_sync(0xffffffffu, s1, 1);
            tacc[2*rp]   = s0;
            tacc[2*rp+1] = s1;
        }

        // ---- store: q==0 lanes hold 4 consecutive t values -> 1 STG.128
        if (q == 0) {
            float* dst = g_t + b*VV + base_v + t*TR + rbase;
            ((float4*)dst)[0] = make_float4(tacc[0], tacc[1], tacc[2], tacc[3]);
        }

        __syncthreads();                               // buffer free for reuse
        if (t + 2 < TILES) load_tile(buf, t + 2);
    }
}

// Fused attention: logits -> exp (no max shift; logits are O(10) by construction)
// -> scatter unnormalized e into g_w, accumulate per-b sum via one block atomic.
__global__ void __launch_bounds__(256) k_att(const int* __restrict__ story) {
    const int i = blockIdx.x*256 + threadIdx.x;
    const int b = i >> 12;
    int4 tk = load_toks(story, i);
    const float* tb = g_t + b*VV;
    float val = tb[tk.x] + tb[tk.y] + tb[tk.z] + tb[tk.w];
    float e = __expf(val);

    float s = e;
    #pragma unroll
    for (int o = 16; o; o >>= 1) s += __shfl_xor_sync(0xffffffffu, s, o);
    __shared__ float sw[8];
    const int lane = threadIdx.x & 31, wid = threadIdx.x >> 5;
    if (lane == 0) sw[wid] = s;
    __syncthreads();
    if (threadIdx.x == 0) {
        float t = 0.f;
        #pragma unroll
        for (int k = 0; k < 8; k++) t += sw[k];
        atomicAdd(&g_sum[b], t);
    }

    float* wb = g_w + b*VV;
    atomicAdd(&wb[tk.x], e);
    atomicAdd(&wb[tk.y], e);
    atomicAdd(&wb[tk.z], e);
    atomicAdd(&wb[tk.w], e);
}

// u[b][d] += sum_v (w[b][v]/sum[b]) * C_next[v][d]
// 500 blocks x 256 threads; block covers UVC=64 vocab rows for all 16 b.
#define UVC 64
__global__ void __launch_bounds__(256) k_update(const float* __restrict__ Cn) {
    __shared__ __align__(16) float wsh[BB][UVC];
    __shared__ float sinv[BB];
    const int tid = threadIdx.x;
    const int d   = tid & 127;
    const int b0  = (tid >> 7) * 8;
    const int v0  = blockIdx.x * UVC;

    if (tid < BB) sinv[tid] = 1.0f / g_sum[tid];
    __syncthreads();
    #pragma unroll
    for (int j = tid; j < BB*UVC; j += 256) {
        int b = j >> 6, vi = j & (UVC-1);
        wsh[b][vi] = g_w[b*VV + v0 + vi] * sinv[b];
    }
    __syncthreads();

    float acc[8];
    #pragma unroll
    for (int b = 0; b < 8; b++) acc[b] = 0.f;

    const float* base = Cn + (size_t)v0 * DD + d;

    #pragma unroll 2
    for (int vi4 = 0; vi4 < UVC/4; vi4++) {
        float c0 = base[(size_t)(vi4*4 + 0) * DD];
        float c1 = base[(size_t)(vi4*4 + 1) * DD];
        float c2 = base[(size_t)(vi4*4 + 2) * DD];
        float c3 = base[(size_t)(vi4*4 + 3) * DD];
        #pragma unroll
        for (int b = 0; b < 8; b++) {
            float4 w = ((const float4*)wsh[b0 + b])[vi4];
            acc[b] += w.x*c0;
            acc[b] += w.y*c1;
            acc[b] += w.z*c2;
            acc[b] += w.w*c3;
        }
    }

    #pragma unroll
    for (int b = 0; b < 8; b++)
        atomicAdd(&g_u[(b0 + b)*DD + d], acc[b]);
}

// final-hop logits straight to output
__global__ void __launch_bounds__(256) k_logits_out(const int* __restrict__ story,
                                                    float* __restrict__ out) {
    const int i = blockIdx.x*256 + threadIdx.x;
    const int b = i >> 12;
    int4 tk = load_toks(story, i);
    const float* tb = g_t + b*VV;
    out[i] = tb[tk.x] + tb[tk.y] + tb[tk.z] + tb[tk.w];
}

// ---------------- launch ----------------
extern "C" void kernel_launch(void* const* d_in, const int* in_sizes, int n_in,
                              void* d_out, int out_size) {
    const int*   story = (const int*)d_in[0];
    const float* q     = (const float*)d_in[1];
    const float* C     = (const float*)d_in[2];
    float* out = (float*)d_out;     // [prob_lg: B*M][u1: B*D]

    const float* C0 = C;
    const float* C1 = C + (size_t)VV * DD;
    const float* C2 = C + 2 * (size_t)VV * DD;

    // ---- hop 0 (u = q read directly; also inits g_u, dtype flag, zeros w) ----
    k_dot<true,  true,  false, false><<<500, DOT_T>>>(C0, q, nullptr, story);
    k_att<<<BM/256, 256>>>(story);
    k_update<<<VV/UVC, 256>>>(C1);

    // ---- hop 1 (dot also emits u1 = g_u to out) ----
    k_dot<false, true,  true,  true ><<<500, DOT_T>>>(C1, nullptr, out + BM, story);
    k_att<<<BM/256, 256>>>(story);
    k_update<<<VV/UVC, 256>>>(C2);

    // ---- hop 2: only logits needed (they ARE prob_lg) ----
    k_dot<false, false, false, true ><<<500, DOT_T>>>(C2, nullptr, nullptr, story);
    k_logits_out<<<BM/256, 256>>>(story, out);
}

// round 10
// speedup vs baseline: 1.2030x; 1.2030x over previous
#include <cuda_runtime.h>
#include <cstdint>

#define BB 16
#define DD 128
#define MM 4096
#define VV 32000
#define BM (BB*MM)

// ---------------- scratch (static device globals; no allocation) ----------------
__device__ __align__(16) float g_u[BB*DD];   // current query u  [B][D]
__device__ __align__(16) float g_t[BB*VV];   // score table t[b][v] = C_h[v].u[b]
__device__ __align__(16) float g_w[BB*VV];   // scattered (unnormalized) exp weights
__device__ float g_sum[BB];                  // softmax denominators
__device__ int g_is64;                       // story dtype flag (1 if int64)

// ---------------- helpers ----------------
__device__ __forceinline__ int4 load_toks(const int* __restrict__ story, int idx) {
    if (!g_is64) {
        return ((const int4*)story)[idx];
    } else {
        longlong4 l = ((const longlong4*)story)[idx];
        return make_int4((int)l.x, (int)l.y, (int)l.z, (int)l.w);
    }
}

__device__ __forceinline__ uint64_t packf2(float x, float y) {
    uint64_t r;
    asm("mov.b64 %0, {%1, %2};" : "=l"(r) : "f"(x), "f"(y));
    return r;
}
__device__ __forceinline__ void unpackf2(uint64_t v, float& x, float& y) {
    asm("mov.b64 {%0, %1}, %2;" : "=f"(x), "=f"(y) : "l"(v));
}
// packed dual-FMA: acc.{lo,hi} += a.{lo,hi} * b.{lo,hi}
__device__ __forceinline__ void ffma2(uint64_t& acc, uint64_t a, uint64_t b) {
    asm("fma.rn.f32x2 %0, %1, %2, %0;" : "+l"(acc) : "l"(a), "l"(b));
}

// ---------------- kernels ----------------

#define TILES 4          // tiles per block
#define TR    16         // rows per tile

// t[b][v] = dot(C_h[v], u[b]) for all v,b.   Grid MUST be 500 x 128.
// R7 pipeline (4 tiles of 16 rows, double-buffered cp.async, load tile t+2
// while computing tile t). Smem row layout: 4 quarters x 9 ulonglong2 slots
// (1 pad slot per quarter) -> quarter q starts at bank 4q, element j at bank
// 4(q+j) mod 32: conflict-free across the 4 quarter-groups with COMPILE-TIME
// indices, so ptxas can front-batch all LDS of a row-pair (the R7-R9 dynamic
// stagger blocked hoisting -> serial ALU->LDS->FFMA chains -> 16% issue).
// Warp layout per tile:
//   rowgrp = warp>>1 -> rows [8*rowgrp, 8*rowgrp+8) ; bgrp = warp&1 -> b range
//   lane: b = bgrp*8 + (lane>>2), quarter q = lane&3 -> dims [32q, 32q+32)
template <bool FIRST, bool ZERO_W, bool COPY_U, bool USE_GU>
__global__ void __launch_bounds__(128) k_dot(const float* __restrict__ Ch,
                                             const float* __restrict__ uin,
                                             float* __restrict__ u_out,
                                             const int* __restrict__ story) {
    if (ZERO_W) {
        const int nt = gridDim.x * 128;                // 64000 threads
        for (int j = blockIdx.x*128 + threadIdx.x; j < BB*VV/4; j += nt)
            ((float4*)g_w)[j] = make_float4(0.f, 0.f, 0.f, 0.f);
        if (blockIdx.x == 0 && threadIdx.x < BB) g_sum[threadIdx.x] = 0.f;
    }
    if (FIRST && blockIdx.x == 0) {
        for (int j = threadIdx.x; j < BB*DD; j += 128) g_u[j] = uin[j];
        if (threadIdx.x == 0) {
            // int64 little-endian: odd words are high words of small tokens -> 0
            int z = story[1] | story[3] | story[5] | story[7];
            g_is64 = (z == 0) ? 1 : 0;
        }
    }
    if (COPY_U && blockIdx.x == 0) {
        for (int j = threadIdx.x; j < BB*DD; j += 128) u_out[j] = g_u[j];
    }

    // [buf][row][quarter][slot] ; 9th slot per quarter is padding
    __shared__ __align__(16) ulonglong2 rowbuf[2][TR][4][9];   // 2 x 9KB

    const int tid  = threadIdx.x;
    const int warp = tid >> 5;
    const int lane = tid & 31;
    const int rowgrp = warp >> 1;
    const int bgrp   = warp & 1;
    const int b      = bgrp*8 + (lane >> 2);
    const int q      = lane & 3;
    const int rbase  = rowgrp * 8;

    const int base_v = blockIdx.x * (TILES*TR);

    const int c_row0 = tid >> 5;
    const int c_col  = tid & 31;
    // padded smem slot for float4 column c: quarter c>>3, pos c&7
    const int c_slot = (c_col >> 3) * 9 + (c_col & 7);

    // ---- async tile loader: tile tt -> buffer buf (one commit group per tile)
    auto load_tile = [&](int buf, int tt) {
        uint32_t sbase = (uint32_t)__cvta_generic_to_shared(&rowbuf[buf][0][0][0]);
        const float* src = Ch + (size_t)(base_v + tt*TR) * DD;
        #pragma unroll
        for (int k = 0; k < 4; k++) {
            const int row = c_row0 + k*4;
            const float4* gp = (const float4*)(src + (size_t)row * DD) + c_col;
            uint32_t sp = sbase + (row*36 + c_slot)*16;
            asm volatile("cp.async.cg.shared.global [%0], [%1], 16;\n"
                         :: "r"(sp), "l"(gp));
        }
        asm volatile("cp.async.commit_group;\n");
    };

    load_tile(0, 0);

    // ---- u registers (overlap with first load): quarter = 32 floats
    uint64_t ureg[16];
    {
        const float4* u4 = USE_GU ? (const float4*)g_u : (const float4*)uin;
        #pragma unroll
        for (int s = 0; s < 8; s++) {
            float4 uu = u4[b*32 + q*8 + s];          // dims 32q+4s..+3
            ureg[2*s]   = packf2(uu.x, uu.y);
            ureg[2*s+1] = packf2(uu.z, uu.w);
        }
    }

    load_tile(1, 1);

    #pragma unroll
    for (int t = 0; t < TILES; t++) {
        const int buf = t & 1;
        if (t < TILES - 1) asm volatile("cp.async.wait_group 1;\n" ::: "memory");
        else               asm volatile("cp.async.wait_group 0;\n" ::: "memory");
        __syncthreads();

        // ---- compute 8 rows as 4 interleaved row-pairs; static smem indices
        float tacc[8];
        #pragma unroll
        for (int rp = 0; rp < 4; rp++) {
            uint64_t a00 = packf2(0.f, 0.f), a01 = packf2(0.f, 0.f);
            uint64_t a10 = packf2(0.f, 0.f), a11 = packf2(0.f, 0.f);
            const ulonglong2* r0 = rowbuf[buf][rbase + 2*rp][q];
            const ulonglong2* r1 = rowbuf[buf][rbase + 2*rp + 1][q];
            #pragma unroll
            for (int j = 0; j < 8; j++) {            // compile-time j -> hoistable
                ulonglong2 c0 = r0[j];
                ulonglong2 c1 = r1[j];
                ffma2(a00, c0.x, ureg[2*j]);
                ffma2(a10, c1.x, ureg[2*j]);
                ffma2(a01, c0.y, ureg[2*j+1]);
                ffma2(a11, c1.y, ureg[2*j+1]);
            }
            float x0, x1, x2, x3, y0, y1, y2, y3;
            unpackf2(a00, x0, x1); unpackf2(a01, x2, x3);
            unpackf2(a10, y0, y1); unpackf2(a11, y2, y3);
            float s0 = (x0 + x1) + (x2 + x3);
            float s1 = (y0 + y1) + (y2 + y3);
            s0 += __shfl_down_sync(0xffffffffu, s0, 2);
            s1 += __shfl_down_sync(0xffffffffu, s1, 2);
            s0 += __shfl_down_sync(0xffffffffu, s0, 1);
            s1 += __shfl_down_sync(0xffffffffu, s1, 1);
            tacc[2*rp]   = s0;
            tacc[2*rp+1] = s1;
        }

        // ---- store: q==0 lanes hold 8 consecutive t values -> 2 STG.128
        if (q == 0) {
            float* dst = g_t + b*VV + base_v + t*TR + rbase;
            ((float4*)dst)[0] = make_float4(tacc[0], tacc[1], tacc[2], tacc[3]);
            ((float4*)dst)[1] = make_float4(tacc[4], tacc[5], tacc[6], tacc[7]);
        }

        __syncthreads();                             // buffer free for reuse
        if (t + 2 < TILES) load_tile(buf, t + 2);
    }
}

// Fused attention: logits -> exp (no max shift; logits are O(10) by construction)
// -> scatter unnormalized e into g_w, accumulate per-b sum via one block atomic.
__global__ void __launch_bounds__(256) k_att(const int* __restrict__ story) {
    const int i = blockIdx.x*256 + threadIdx.x;
    const int b = i >> 12;
    int4 tk = load_toks(story, i);
    const float* tb = g_t + b*VV;
    float val = tb[tk.x] + tb[tk.y] + tb[tk.z] + tb[tk.w];
    float e = __expf(val);

    float s = e;
    #pragma unroll
    for (int o = 16; o; o >>= 1) s += __shfl_xor_sync(0xffffffffu, s, o);
    __shared__ float sw[8];
    const int lane = threadIdx.x & 31, wid = threadIdx.x >> 5;
    if (lane == 0) sw[wid] = s;
    __syncthreads();
    if (threadIdx.x == 0) {
        float t = 0.f;
        #pragma unroll
        for (int k = 0; k < 8; k++) t += sw[k];
        atomicAdd(&g_sum[b], t);
    }

    float* wb = g_w + b*VV;
    atomicAdd(&wb[tk.x], e);
    atomicAdd(&wb[tk.y], e);
    atomicAdd(&wb[tk.z], e);
    atomicAdd(&wb[tk.w], e);
}

// u[b][d] += sum_v (w[b][v]/sum[b]) * C_next[v][d]
// 500 blocks x 256 threads; block covers UVC=64 vocab rows for all 16 b.
#define UVC 64
__global__ void __launch_bounds__(256) k_update(const float* __restrict__ Cn) {
    __shared__ __align__(16) float wsh[BB][UVC];
    __shared__ float sinv[BB];
    const int tid = threadIdx.x;
    const int d   = tid & 127;
    const int b0  = (tid >> 7) * 8;
    const int v0  = blockIdx.x * UVC;

    if (tid < BB) sinv[tid] = 1.0f / g_sum[tid];
    __syncthreads();
    #pragma unroll
    for (int j = tid; j < BB*UVC; j += 256) {
        int b = j >> 6, vi = j & (UVC-1);
        wsh[b][vi] = g_w[b*VV + v0 + vi] * sinv[b];
    }
    __syncthreads();

    float acc[8];
    #pragma unroll
    for (int b = 0; b < 8; b++) acc[b] = 0.f;

    const float* base = Cn + (size_t)v0 * DD + d;

    #pragma unroll 2
    for (int vi4 = 0; vi4 < UVC/4; vi4++) {
        float c0 = base[(size_t)(vi4*4 + 0) * DD];
        float c1 = base[(size_t)(vi4*4 + 1) * DD];
        float c2 = base[(size_t)(vi4*4 + 2) * DD];
        float c3 = base[(size_t)(vi4*4 + 3) * DD];
        #pragma unroll
        for (int b = 0; b < 8; b++) {
            float4 w = ((const float4*)wsh[b0 + b])[vi4];
            acc[b] += w.x*c0;
            acc[b] += w.y*c1;
            acc[b] += w.z*c2;
            acc[b] += w.w*c3;
        }
    }

    #pragma unroll
    for (int b = 0; b < 8; b++)
        atomicAdd(&g_u[(b0 + b)*DD + d], acc[b]);
}

// final-hop logits straight to output
__global__ void __launch_bounds__(256) k_logits_out(const int* __restrict__ story,
                                                    float* __restrict__ out) {
    const int i = blockIdx.x*256 + threadIdx.x;
    const int b = i >> 12;
    int4 tk = load_toks(story, i);
    const float* tb = g_t + b*VV;
    out[i] = tb[tk.x] + tb[tk.y] + tb[tk.z] + tb[tk.w];
}

// ---------------- launch ----------------
extern "C" void kernel_launch(void* const* d_in, const int* in_sizes, int n_in,
                              void* d_out, int out_size) {
    const int*   story = (const int*)d_in[0];
    const float* q     = (const float*)d_in[1];
    const float* C     = (const float*)d_in[2];
    float* out = (float*)d_out;     // [prob_lg: B*M][u1: B*D]

    const float* C0 = C;
    const float* C1 = C + (size_t)VV * DD;
    const float* C2 = C + 2 * (size_t)VV * DD;

    // ---- hop 0 (u = q read directly; also inits g_u, dtype flag, zeros w) ----
    k_dot<true,  true,  false, false><<<500, 128>>>(C0, q, nullptr, story);
    k_att<<<BM/256, 256>>>(story);
    k_update<<<VV/UVC, 256>>>(C1);

    // ---- hop 1 (dot also emits u1 = g_u to out) ----
    k_dot<false, true,  true,  true ><<<500, 128>>>(C1, nullptr, out + BM, story);
    k_att<<<BM/256, 256>>>(story);
    k_update<<<VV/UVC, 256>>>(C2);

    // ---- hop 2: only logits needed (they ARE prob_lg) ----
    k_dot<false, false, false, true ><<<500, 128>>>(C2, nullptr, nullptr, story);
    k_logits_out<<<BM/256, 256>>>(story, out);
}

// round 11
// speedup vs baseline: 1.6896x; 1.4045x over previous
#include <cuda_runtime.h>
#include <cstdint>

#define BB 16
#define DD 128
#define MM 4096
#define VV 32000
#define BM (BB*MM)

// ---------------- scratch (static device globals; no allocation) ----------------
__device__ __align__(16) float g_u[BB*DD];   // current query u  [B][D]
__device__ __align__(16) float g_t[BB*VV];   // score table t[b][v] = C_h[v].u[b]
__device__ __align__(16) float g_w[BB*VV];   // scattered (unnormalized) exp weights
__device__ float g_sum[BB];                  // softmax denominators
__device__ int g_is64;                       // story dtype flag (1 if int64)

// ---------------- helpers ----------------
__device__ __forceinline__ int4 load_toks(const int* __restrict__ story, int idx) {
    if (!g_is64) {
        return ((const int4*)story)[idx];
    } else {
        longlong4 l = ((const longlong4*)story)[idx];
        return make_int4((int)l.x, (int)l.y, (int)l.z, (int)l.w);
    }
}

// pack2(hi,lo): bf16x2 with .lo = bf16(lo), .hi = bf16(hi)
__device__ __forceinline__ uint32_t pack2(float hi, float lo) {
    uint32_t r;
    asm("cvt.rn.bf16x2.f32 %0, %1, %2;" : "=r"(r) : "f"(hi), "f"(lo));
    return r;
}
__device__ __forceinline__ float lo_f(uint32_t p) { return __uint_as_float(p << 16); }
__device__ __forceinline__ float hi_f(uint32_t p) { return __uint_as_float(p & 0xffff0000u); }

#define LDSM4(r0,r1,r2,r3,addr) \
  asm volatile("ldmatrix.sync.aligned.m8n8.x4.shared.b16 {%0,%1,%2,%3}, [%4];" \
               : "=r"(r0),"=r"(r1),"=r"(r2),"=r"(r3) : "r"(addr))

#define MMA16816(d0,d1,d2,d3,a0,a1,a2,a3,b0,b1) \
  asm volatile("mma.sync.aligned.m16n8k16.row.col.f32.bf16.bf16.f32 " \
               "{%0,%1,%2,%3}, {%4,%5,%6,%7}, {%8,%9}, {%0,%1,%2,%3};" \
               : "+f"(d0),"+f"(d1),"+f"(d2),"+f"(d3) \
               : "r"(a0),"r"(a1),"r"(a2),"r"(a3),"r"(b0),"r"(b1))

// smem: SF0 fp32 tile (16KB) | SF1 fp32 tile (16KB) | CHs bf16 (8.5KB) | CLs (8.5KB)
// TS (16x36 f32, 2.3KB) aliases SF0 (dead after its tile's conversion).
#define SMEM_BYTES (32768 + 8704 + 8704)

// ---------------- kernels ----------------

// t[b][v] = dot(C_h[v], u[b]) via split-bf16 tensor-core MMA.
// Grid MUST be 500 x 128. Block covers 64 rows = 2 tiles of 32 rows,
// double-buffered cp.async fp32 staging.
// Warp roles: tile16 = warp>>1 (rows 16*tile16..+16), ngrp = warp&1 (b 8*ngrp..+8).
// Per tile: fp32 -> bf16 hi/lo split in smem (padded 136-col rows for
// conflict-free ldmatrix), then 8 ksteps x (2 ldmatrix.x4 + 3 mma):
//   D += Ch*uh + Cl*uh + Ch*ul   (residual ~2e-5 relative)
template <bool FIRST, bool ZERO_W, bool COPY_U, bool USE_GU>
__global__ void __launch_bounds__(128) k_dot(const float* __restrict__ Cg,
                                             const float* __restrict__ uin,
                                             float* __restrict__ u_out,
                                             const int* __restrict__ story) {
    extern __shared__ __align__(16) char smem_raw[];
    float4*   SF0 = (float4*)smem_raw;                 // [32][32] float4
    float4*   SF1 = SF0 + 32*32;
    uint16_t* CHs = (uint16_t*)(SF1 + 32*32);          // [32][136] bf16
    uint16_t* CLs = CHs + 32*136;
    float*    TS  = (float*)smem_raw;                  // [16][36] (aliases SF0)

    const int tid  = threadIdx.x;
    const int warp = tid >> 5;
    const int lane = tid & 31;

    if (ZERO_W) {
        const int nt = gridDim.x * 128;                // 64000 threads, 2 iters
        for (int j = blockIdx.x*128 + tid; j < BB*VV/4; j += nt)
            ((float4*)g_w)[j] = make_float4(0.f, 0.f, 0.f, 0.f);
        if (blockIdx.x == 0 && tid < BB) g_sum[tid] = 0.f;
    }
    if (FIRST && blockIdx.x == 0) {
        for (int j = tid; j < BB*DD; j += 128) g_u[j] = uin[j];
        if (tid == 0) {
            // int64 little-endian: odd words are high words of small tokens -> 0
            int z = story[1] | story[3] | story[5] | story[7];
            g_is64 = (z == 0) ? 1 : 0;
        }
    }
    if (COPY_U && blockIdx.x == 0) {
        for (int j = tid; j < BB*DD; j += 128) u_out[j] = g_u[j];
    }

    const int v0 = blockIdx.x * 64;

    auto load_tile = [&](float4* SF, int tt) {
        uint32_t sb = (uint32_t)__cvta_generic_to_shared(SF);
        const float4* src = (const float4*)(Cg + (size_t)(v0 + tt*32) * DD);
        #pragma unroll
        for (int k = 0; k < 8; k++) {
            int c = tid + k*128;
            asm volatile("cp.async.cg.shared.global [%0], [%1], 16;\n"
                         :: "r"(sb + c*16), "l"(src + c));
        }
        asm volatile("cp.async.commit_group;\n");
    };

    load_tile(SF0, 0);

    // ---- B fragments (u split hi/lo) held in registers, built from fp32 u.
    // b0 reg: k = 2*(lane&3)+{0,1}; b1 reg: k+8 ; n = lane>>2 within ngrp.
    const int ngrp   = warp & 1;
    const int tile16 = warp >> 1;
    const int bidx   = ngrp*8 + (lane >> 2);

    uint32_t Bh0[8], Bh1[8], Bl0[8], Bl1[8];
    {
        const float* usrc = USE_GU ? g_u : uin;
        const float2* u2 = (const float2*)(usrc + bidx*DD);
        #pragma unroll
        for (int k = 0; k < 8; k++) {
            float2 p = u2[8*k + (lane&3)];
            float2 r = u2[8*k + 4 + (lane&3)];
            uint32_t hp = pack2(p.y, p.x);
            Bh0[k] = hp;
            Bl0[k] = pack2(p.y - hi_f(hp), p.x - lo_f(hp));
            uint32_t hr = pack2(r.y, r.x);
            Bh1[k] = hr;
            Bl1[k] = pack2(r.y - hi_f(hr), r.x - lo_f(hr));
        }
    }

    load_tile(SF1, 1);

    // ldmatrix lane address: row = lane&15 of this warp's 16-row tile,
    // col chunk = (lane>>4)*8 bf16 ; row stride 272B (136 bf16, conflict-free)
    const uint32_t aoff = (uint32_t)((tile16*16 + (lane & 15))*272 + ((lane >> 4)*8)*2);
    const uint32_t ch_base = (uint32_t)__cvta_generic_to_shared(CHs) + aoff;
    const uint32_t cl_base = (uint32_t)__cvta_generic_to_shared(CLs) + aoff;

    #pragma unroll
    for (int t = 0; t < 2; t++) {
        if (t == 0) asm volatile("cp.async.wait_group 1;\n" ::: "memory");
        else        asm volatile("cp.async.wait_group 0;\n" ::: "memory");
        __syncthreads();

        // ---- fp32 -> bf16 hi/lo split into padded smem (8 float4 per thread)
        const float4* SF = t ? SF1 : SF0;
        #pragma unroll
        for (int k = 0; k < 8; k++) {
            int c = tid + k*128;
            int row = c >> 5, col = c & 31;
            float4 f = SF[c];
            uint32_t h01 = pack2(f.y, f.x);
            uint32_t h23 = pack2(f.w, f.z);
            uint32_t l01 = pack2(f.y - hi_f(h01), f.x - lo_f(h01));
            uint32_t l23 = pack2(f.w - hi_f(h23), f.z - lo_f(h23));
            *(uint2*)(CHs + row*136 + col*4) = make_uint2(h01, h23);
            *(uint2*)(CLs + row*136 + col*4) = make_uint2(l01, l23);
        }
        __syncthreads();

        // ---- MMA: 8 ksteps x 3 combos
        float d0 = 0.f, d1 = 0.f, d2 = 0.f, d3 = 0.f;
        #pragma unroll
        for (int k = 0; k < 8; k++) {
            uint32_t ah0, ah1, ah2, ah3, al0, al1, al2, al3;
            LDSM4(ah0, ah1, ah2, ah3, ch_base + k*32);
            LDSM4(al0, al1, al2, al3, cl_base + k*32);
            MMA16816(d0, d1, d2, d3, ah0, ah1, ah2, ah3, Bh0[k], Bh1[k]);
            MMA16816(d0, d1, d2, d3, al0, al1, al2, al3, Bh0[k], Bh1[k]);
            MMA16816(d0, d1, d2, d3, ah0, ah1, ah2, ah3, Bl0[k], Bl1[k]);
        }

        // ---- stage D to TS[b][v_local] (padded [16][36], conflict-free)
        {
            int row0 = lane >> 2, colb = (lane & 3)*2;
            int vloc = tile16*16 + row0;
            TS[(ngrp*8 + colb    )*36 + vloc    ] = d0;
            TS[(ngrp*8 + colb + 1)*36 + vloc    ] = d1;
            TS[(ngrp*8 + colb    )*36 + vloc + 8] = d2;
            TS[(ngrp*8 + colb + 1)*36 + vloc + 8] = d3;
        }
        __syncthreads();

        // ---- coalesced store: thread (b = tid>>3, chunk = tid&7) -> STG.128
        {
            int b = tid >> 3, chn = tid & 7;
            float4 val = *(float4*)&TS[b*36 + chn*4];
            *(float4*)(g_t + b*VV + v0 + t*32 + chn*4) = val;
        }
    }
}

// Fused attention: logits -> exp (no max shift; logits are O(10) by construction)
// -> scatter unnormalized e into g_w, accumulate per-b sum via one block atomic.
__global__ void __launch_bounds__(256) k_att(const int* __restrict__ story) {
    const int i = blockIdx.x*256 + threadIdx.x;
    const int b = i >> 12;
    int4 tk = load_toks(story, i);
    const float* tb = g_t + b*VV;
    float val = tb[tk.x] + tb[tk.y] + tb[tk.z] + tb[tk.w];
    float e = __expf(val);

    float s = e;
    #pragma unroll
    for (int o = 16; o; o >>= 1) s += __shfl_xor_sync(0xffffffffu, s, o);
    __shared__ float sw[8];
    const int lane = threadIdx.x & 31, wid = threadIdx.x >> 5;
    if (lane == 0) sw[wid] = s;
    __syncthreads();
    if (threadIdx.x == 0) {
        float t = 0.f;
        #pragma unroll
        for (int k = 0; k < 8; k++) t += sw[k];
        atomicAdd(&g_sum[b], t);
    }

    float* wb = g_w + b*VV;
    atomicAdd(&wb[tk.x], e);
    atomicAdd(&wb[tk.y], e);
    atomicAdd(&wb[tk.z], e);
    atomicAdd(&wb[tk.w], e);
}

// u[b][d] += sum_v (w[b][v]/sum[b]) * C_next[v][d]
// 500 blocks x 256 threads; block covers UVC=64 vocab rows for all 16 b.
#define UVC 64
__global__ void __launch_bounds__(256) k_update(const float* __restrict__ Cn) {
    __shared__ __align__(16) float wsh[BB][UVC];
    __shared__ float sinv[BB];
    const int tid = threadIdx.x;
    const int d   = tid & 127;
    const int b0  = (tid >> 7) * 8;
    const int v0  = blockIdx.x * UVC;

    if (tid < BB) sinv[tid] = 1.0f / g_sum[tid];
    __syncthreads();
    #pragma unroll
    for (int j = tid; j < BB*UVC; j += 256) {
        int b = j >> 6, vi = j & (UVC-1);
        wsh[b][vi] = g_w[b*VV + v0 + vi] * sinv[b];
    }
    __syncthreads();

    float acc[8];
    #pragma unroll
    for (int b = 0; b < 8; b++) acc[b] = 0.f;

    const float* base = Cn + (size_t)v0 * DD + d;

    #pragma unroll 2
    for (int vi4 = 0; vi4 < UVC/4; vi4++) {
        float c0 = base[(size_t)(vi4*4 + 0) * DD];
        float c1 = base[(size_t)(vi4*4 + 1) * DD];
        float c2 = base[(size_t)(vi4*4 + 2) * DD];
        float c3 = base[(size_t)(vi4*4 + 3) * DD];
        #pragma unroll
        for (int b = 0; b < 8; b++) {
            float4 w = ((const float4*)wsh[b0 + b])[vi4];
            acc[b] += w.x*c0;
            acc[b] += w.y*c1;
            acc[b] += w.z*c2;
            acc[b] += w.w*c3;
        }
    }

    #pragma unroll
    for (int b = 0; b < 8; b++)
        atomicAdd(&g_u[(b0 + b)*DD + d], acc[b]);
}

// final-hop logits straight to output
__global__ void __launch_bounds__(256) k_logits_out(const int* __restrict__ story,
                                                    float* __restrict__ out) {
    const int i = blockIdx.x*256 + threadIdx.x;
    const int b = i >> 12;
    int4 tk = load_toks(story, i);
    const float* tb = g_t + b*VV;
    out[i] = tb[tk.x] + tb[tk.y] + tb[tk.z] + tb[tk.w];
}

// ---------------- launch ----------------
extern "C" void kernel_launch(void* const* d_in, const int* in_sizes, int n_in,
                              void* d_out, int out_size) {
    const int*   story = (const int*)d_in[0];
    const float* q     = (const float*)d_in[1];
    const float* C     = (const float*)d_in[2];
    float* out = (float*)d_out;     // [prob_lg: B*M][u1: B*D]

    const float* C0 = C;
    const float* C1 = C + (size_t)VV * DD;
    const float* C2 = C + 2 * (size_t)VV * DD;

    // raise dynamic smem cap (idempotent; no allocation)
    cudaFuncSetAttribute(k_dot<true,  true,  false, false>,
                         cudaFuncAttributeMaxDynamicSharedMemorySize, SMEM_BYTES);
    cudaFuncSetAttribute(k_dot<false, true,  true,  true >,
                         cudaFuncAttributeMaxDynamicSharedMemorySize, SMEM_BYTES);
    cudaFuncSetAttribute(k_dot<false, false, false, true >,
                         cudaFuncAttributeMaxDynamicSharedMemorySize, SMEM_BYTES);

    // ---- hop 0 (u = q read directly; also inits g_u, dtype flag, zeros w) ----
    k_dot<true,  true,  false, false><<<500, 128, SMEM_BYTES>>>(C0, q, nullptr, story);
    k_att<<<BM/256, 256>>>(story);
    k_update<<<VV/UVC, 256>>>(C1);

    // ---- hop 1 (dot also emits u1 = g_u to out) ----
    k_dot<false, true,  true,  true ><<<500, 128, SMEM_BYTES>>>(C1, nullptr, out + BM, story);
    k_att<<<BM/256, 256>>>(story);
    k_update<<<VV/UVC, 256>>>(C2);

    // ---- hop 2: only logits needed (they ARE prob_lg) ----
    k_dot<false, false, false, true ><<<500, 128, SMEM_BYTES>>>(C2, nullptr, nullptr, story);
    k_logits_out<<<BM/256, 256>>>(story, out);
}